// round 2
// baseline (speedup 1.0000x reference)
#include <cuda_runtime.h>
#include <math.h>

#define B  16
#define T  128
#define S  128
#define NH 64
#define DH 128
#define TS 8       // owned sites per block
#define NS 9       // computed sites (own + 1 left-halo site)
#define NQ 11      // prev-state halo sites (s0-2 .. s0+TS)
#define TPB 256
#define TOUT 107   // T-1-20

// Persistent double-buffered recurrent state
__device__ float g_hn[2][B*S*NH];
__device__ float g_cn[2][B*S*NH];
__device__ float g_hs[2][B*S*NH];
__device__ float g_cs[2][B*S*NH];
__device__ float g_hd[2][B*S*DH];
__device__ float g_cd[2][B*S*DH];

// shared memory layout (in floats)
#define OFF_HNP 0
#define OFF_HSP (OFF_HNP + NQ*NH)
#define OFF_HDP (OFF_HSP + NQ*NH)
#define OFF_HNC (OFF_HDP + NQ*DH)
#define OFF_HSC (OFF_HNC + NS*NH)
#define OFF_HDC (OFF_HSC + NS*NH)
#define OFF_GN  (OFF_HDC + NS*DH)
#define OFF_GS  (OFF_GN  + NS*256)
#define OFF_GD  (OFF_GS  + NS*256)
#define OFF_XIN (OFF_GD  + NS*512)
#define OFF_O0  (OFF_XIN + NS*4)
#define OFF_O1  (OFF_O0  + NS)
#define SMEM_FLOATS (OFF_O1 + NS)

__device__ __forceinline__ float sigm(float x) { return 1.f / (1.f + __expf(-x)); }

__global__ void init_states_kernel() {
    int i = blockIdx.x * blockDim.x + threadIdx.x;
    if (i < B*S*NH) {
        g_hn[0][i] = 0.f; g_cn[0][i] = 0.f;
        g_hs[0][i] = 0.f; g_cs[0][i] = 0.f;
    }
    if (i < B*S*DH) {
        g_hd[0][i] = 0.f; g_cd[0][i] = 0.f;
    }
}

__global__ void __launch_bounds__(TPB, 2) step_kernel(
    const float* __restrict__ xg,
    const float* __restrict__ nWx, const float* __restrict__ nWh,
    const float* __restrict__ nWa, const float* __restrict__ nWb,
    const float* __restrict__ nb,
    const float* __restrict__ sWx, const float* __restrict__ sWh,
    const float* __restrict__ sWa, const float* __restrict__ sWb,
    const float* __restrict__ sb,
    const float* __restrict__ dWx, const float* __restrict__ dWh,
    const float* __restrict__ dWa, const float* __restrict__ dWb,
    const float* __restrict__ db,
    const float* __restrict__ onW, const float* __restrict__ onb,
    const float* __restrict__ osW, const float* __restrict__ osb,
    float* __restrict__ out, int t)
{
    extern __shared__ float sm[];
    float* hnp = sm + OFF_HNP;
    float* hsp = sm + OFF_HSP;
    float* hdp = sm + OFF_HDP;
    float* hnc = sm + OFF_HNC;
    float* hsc = sm + OFF_HSC;
    float* hdc = sm + OFF_HDC;
    float* gn  = sm + OFF_GN;
    float* gs  = sm + OFF_GS;
    float* gd  = sm + OFF_GD;
    float* xin = sm + OFF_XIN;
    float* o0s = sm + OFF_O0;
    float* o1s = sm + OFF_O1;

    const int tid = threadIdx.x;
    const int bb  = blockIdx.y;
    const int s0  = blockIdx.x * TS;
    const int pp  = t & 1;
    const int qq  = pp ^ 1;

    // ---- load prev-state halos (sites s0-2 .. s0+TS) ----
    for (int i = tid; i < NQ*NH; i += TPB) {
        int q = i >> 6; int sg = s0 - 2 + q;
        bool v = ((unsigned)sg < (unsigned)S);
        int gi = (bb*S + sg) * NH + (i & 63);
        hnp[i] = v ? g_hn[pp][gi] : 0.f;
        hsp[i] = v ? g_hs[pp][gi] : 0.f;
    }
    for (int i = tid; i < NQ*DH; i += TPB) {
        int q = i >> 7; int sg = s0 - 2 + q;
        bool v = ((unsigned)sg < (unsigned)S);
        hdp[i] = v ? g_hd[pp][(bb*S + sg) * DH + (i & 127)] : 0.f;
    }
    for (int i = tid; i < NS*4; i += TPB) {
        int r = i >> 2; int sg = s0 - 1 + r;
        xin[i] = ((unsigned)sg < (unsigned)S)
                 ? xg[(((size_t)bb*T + t)*S + sg)*4 + (i & 3)] : 0.f;
    }
    __syncthreads();

    // ---- n & s gates: thread tid computes gate column tid for all NS sites ----
    {
        float an[NS], asv[NS];
        float bn_ = nb[tid], bs_ = sb[tid];
        #pragma unroll
        for (int r = 0; r < NS; r++) { an[r] = bn_; asv[r] = bs_; }
        #pragma unroll
        for (int k = 0; k < 3; k++) {
            float w = nWx[k*256 + tid];
            #pragma unroll
            for (int r = 0; r < NS; r++) an[r] += xin[r*4 + k] * w;
        }
        {
            float w = sWx[tid];
            #pragma unroll
            for (int r = 0; r < NS; r++) asv[r] += xin[r*4 + 3] * w;
        }
        #pragma unroll 4
        for (int k = 0; k < NH; k++) {
            float wh = nWh[k*256 + tid], wa = nWa[k*256 + tid], wb = nWb[k*256 + tid];
            float vh = sWh[k*256 + tid], va = sWa[k*256 + tid], vb = sWb[k*256 + tid];
            #pragma unroll
            for (int q = 0; q < NQ; q++) {
                float hn_ = hnp[q*NH + k], hs_ = hsp[q*NH + k];
                // prev h at global site (s0-2+q) feeds:
                //   Wh -> site r=q-1, Wa -> site r=q-2, Wb -> site r=q
                if (q >= 1 && q <= NS) { an[q-1] += hn_*wh; asv[q-1] += hs_*vh; }
                if (q >= 2)            { an[q-2] += hn_*wa; asv[q-2] += hs_*va; }
                if (q <  NS)           { an[q]   += hn_*wb; asv[q]   += hs_*vb; }
            }
        }
        #pragma unroll
        for (int r = 0; r < NS; r++) { gn[r*256 + tid] = an[r]; gs[r*256 + tid] = asv[r]; }
    }
    __syncthreads();

    // ---- n & s cell updates ----
    for (int i = tid; i < NS*NH; i += TPB) {
        int r = i >> 6, e = i & 63;
        int sg = s0 - 1 + r;
        bool v = ((unsigned)sg < (unsigned)S);
        int gi = v ? (bb*S + sg)*NH + e : 0;
        // n cell
        {
            float ii = gn[r*256 + e],       ff = gn[r*256 + 64 + e];
            float uu = gn[r*256 + 128 + e], oo = gn[r*256 + 192 + e];
            float cp = v ? g_cn[pp][gi] : 0.f;
            float c2 = sigm(ff)*cp + sigm(ii)*tanhf(uu);
            float h  = sigm(oo)*tanhf(c2);
            if (!v) { c2 = 0.f; h = 0.f; }
            hnc[i] = h;
            if (r >= 1) { g_cn[qq][gi] = c2; g_hn[qq][gi] = h; }
        }
        // s cell
        {
            float ii = gs[r*256 + e],       ff = gs[r*256 + 64 + e];
            float uu = gs[r*256 + 128 + e], oo = gs[r*256 + 192 + e];
            float cp = v ? g_cs[pp][gi] : 0.f;
            float c2 = sigm(ff)*cp + sigm(ii)*tanhf(uu);
            float h  = sigm(oo)*tanhf(c2);
            if (!v) { c2 = 0.f; h = 0.f; }
            hsc[i] = h;
            if (r >= 1) { g_cs[qq][gi] = c2; g_hs[qq][gi] = h; }
        }
    }
    __syncthreads();

    // ---- d gates: thread tid computes gate columns tid and tid+256 ----
    {
        float a0[NS], a1[NS];
        float b0 = db[tid], b1 = db[256 + tid];
        #pragma unroll
        for (int r = 0; r < NS; r++) { a0[r] = b0; a1[r] = b1; }
        #pragma unroll 4
        for (int k = 0; k < NH; k++) {
            float w0 = dWx[k*512 + tid], w1 = dWx[k*512 + 256 + tid];
            #pragma unroll
            for (int r = 0; r < NS; r++) {
                float x = hnc[r*NH + k];
                a0[r] += x*w0; a1[r] += x*w1;
            }
        }
        #pragma unroll 4
        for (int k = 0; k < NH; k++) {
            float w0 = dWx[(NH + k)*512 + tid], w1 = dWx[(NH + k)*512 + 256 + tid];
            #pragma unroll
            for (int r = 0; r < NS; r++) {
                float x = hsc[r*NH + k];
                a0[r] += x*w0; a1[r] += x*w1;
            }
        }
        #pragma unroll 2
        for (int k = 0; k < DH; k++) {
            float wh0 = dWh[k*512 + tid], wh1 = dWh[k*512 + 256 + tid];
            float wa0 = dWa[k*512 + tid], wa1 = dWa[k*512 + 256 + tid];
            float wb0 = dWb[k*512 + tid], wb1 = dWb[k*512 + 256 + tid];
            #pragma unroll
            for (int q = 0; q < NQ; q++) {
                float h = hdp[q*DH + k];
                if (q >= 1 && q <= NS) { a0[q-1] += h*wh0; a1[q-1] += h*wh1; }
                if (q >= 2)            { a0[q-2] += h*wa0; a1[q-2] += h*wa1; }
                if (q <  NS)           { a0[q]   += h*wb0; a1[q]   += h*wb1; }
            }
        }
        #pragma unroll
        for (int r = 0; r < NS; r++) {
            gd[r*512 + tid] = a0[r];
            gd[r*512 + 256 + tid] = a1[r];
        }
    }
    __syncthreads();

    // ---- d cell update ----
    for (int i = tid; i < NS*DH; i += TPB) {
        int r = i >> 7, e = i & 127;
        int sg = s0 - 1 + r;
        bool v = ((unsigned)sg < (unsigned)S);
        int gi = v ? (bb*S + sg)*DH + e : 0;
        float ii = gd[r*512 + e],       ff = gd[r*512 + 128 + e];
        float uu = gd[r*512 + 256 + e], oo = gd[r*512 + 384 + e];
        float cp = v ? g_cd[pp][gi] : 0.f;
        float c2 = sigm(ff)*cp + sigm(ii)*tanhf(uu);
        float h  = sigm(oo)*tanhf(c2);
        if (!v) { c2 = 0.f; h = 0.f; }
        hdc[i] = h;
        if (r >= 1) { g_cd[qq][gi] = c2; g_hd[qq][gi] = h; }
    }
    __syncthreads();

    // ---- output heads: o0 = hd @ on_W + on_b ; o1 = hd @ os_W + os_b ----
    if (tid < 2*NS) {
        int r = tid % NS;
        int which = tid / NS;
        const float* W = which ? osW : onW;
        float acc = which ? osb[0] : onb[0];
        #pragma unroll 8
        for (int k = 0; k < DH; k++) acc += hdc[r*DH + k] * W[k];
        if (which) o1s[r] = acc; else o0s[r] = acc;
    }
    __syncthreads();

    // ---- assemble next-input record and write output for t >= 20 ----
    if (t >= 20 && tid >= 1 && tid <= TS) {
        int r = tid;
        int sg = s0 + r - 1;
        float o0 = o0s[r];
        float o1 = o1s[r];
        float inflow, spd;
        if (sg == 0) {
            inflow = xg[(((size_t)bb*T + (t+1))*S + 0)*4 + 1];
            spd    = xg[(((size_t)bb*T + (t+1))*S + 0)*4 + 3];
        } else {
            inflow = o0s[r-1];
            spd    = o1;
        }
        float numc = xin[r*4 + 2] + inflow - o0;
        float* o = out + ((((size_t)bb*TOUT) + (t - 20))*S + sg)*4;
        o[0] = o0; o[1] = inflow; o[2] = numc; o[3] = spd;
    }
}

extern "C" void kernel_launch(void* const* d_in, const int* in_sizes, int n_in,
                              void* d_out, int out_size) {
    const float* xg  = (const float*)d_in[0];
    const float* nWx = (const float*)d_in[1];
    const float* nWh = (const float*)d_in[2];
    const float* nWa = (const float*)d_in[3];
    const float* nWb = (const float*)d_in[4];
    const float* nb  = (const float*)d_in[5];
    const float* sWx = (const float*)d_in[6];
    const float* sWh = (const float*)d_in[7];
    const float* sWa = (const float*)d_in[8];
    const float* sWb = (const float*)d_in[9];
    const float* sb  = (const float*)d_in[10];
    const float* dWx = (const float*)d_in[11];
    const float* dWh = (const float*)d_in[12];
    const float* dWa = (const float*)d_in[13];
    const float* dWb = (const float*)d_in[14];
    const float* db  = (const float*)d_in[15];
    const float* onW = (const float*)d_in[16];
    const float* onb = (const float*)d_in[17];
    const float* osW = (const float*)d_in[18];
    const float* osb = (const float*)d_in[19];
    float* out = (float*)d_out;

    (void)in_sizes; (void)n_in; (void)out_size;

    const int smem_bytes = SMEM_FLOATS * (int)sizeof(float);
    cudaFuncSetAttribute(step_kernel,
                         cudaFuncAttributeMaxDynamicSharedMemorySize, smem_bytes);

    init_states_kernel<<<(B*S*DH + TPB - 1) / TPB, TPB>>>();

    dim3 grid(S / TS, B);
    for (int t = 0; t < T - 1; ++t) {
        step_kernel<<<grid, TPB, smem_bytes>>>(
            xg, nWx, nWh, nWa, nWb, nb,
            sWx, sWh, sWa, sWb, sb,
            dWx, dWh, dWa, dWb, db,
            onW, onb, osW, osb, out, t);
    }
}

// round 3
// speedup vs baseline: 1.2843x; 1.2843x over previous
#include <cuda_runtime.h>
#include <math.h>

typedef unsigned long long ull;

#define B  16
#define T  128
#define S  128
#define NH 64
#define DH 128
#define TS 16      // owned sites per block
#define NS 17      // computed sites (own + 1 left-halo site)
#define NQ 19      // prev-state halo sites (s0-2 .. s0+TS)
#define TPB 512
#define TOUT 107   // T-1-20

// Persistent double-buffered recurrent state
__device__ float g_hn[2][B*S*NH];
__device__ float g_cn[2][B*S*NH];
__device__ float g_hs[2][B*S*NH];
__device__ float g_cs[2][B*S*NH];
__device__ float g_hd[2][B*S*DH];
__device__ float g_cd[2][B*S*DH];

// k-paired weight copies: entry kk holds (W[2kk][c], W[2kk+1][c])
__device__ float2 pnWh2[32*256], pnWa2[32*256], pnWb2[32*256];
__device__ float2 psWh2[32*256], psWa2[32*256], psWb2[32*256];
__device__ float2 pdWx2[64*512], pdWh2[64*512], pdWa2[64*512], pdWb2[64*512];

// shared memory layout (in floats)
#define OFF_HNP 0
#define OFF_HSP (OFF_HNP + NQ*NH)
#define OFF_HDP (OFF_HSP + NQ*NH)
#define OFF_HNC (OFF_HDP + NQ*DH)
#define OFF_HSC (OFF_HNC + NS*NH)
#define OFF_HDC (OFF_HSC + NS*NH)
#define OFF_GN  (OFF_HDC + NS*DH)
#define OFF_GS  (OFF_GN  + NS*256)
#define OFF_GD  (OFF_GS  + NS*256)
#define OFF_XIN (OFF_GD  + NS*512)
#define OFF_O0  (OFF_XIN + NS*4)
#define OFF_O1  (OFF_O0  + NS)
#define SMEM_FLOATS (OFF_O1 + NS)

#define FMA2(acc, a, b) asm("fma.rn.f32x2 %0, %1, %2, %0;" : "+l"(acc) : "l"(a), "l"(b))
#define UNPACK2(lo, hi, v) asm("mov.b64 {%0, %1}, %2;" : "=f"(lo), "=f"(hi) : "l"(v))

__device__ __forceinline__ ull ld2g(const float2* p, int i) {
    return *reinterpret_cast<const ull*>(p + i);
}
__device__ __forceinline__ ull ld2s(const float* p) {
    return *reinterpret_cast<const ull*>(p);
}

__device__ __forceinline__ float sigm(float x) { return 1.f / (1.f + __expf(-x)); }

__global__ void init_states_kernel() {
    int i = blockIdx.x * blockDim.x + threadIdx.x;
    if (i < B*S*NH) {
        g_hn[0][i] = 0.f; g_cn[0][i] = 0.f;
        g_hs[0][i] = 0.f; g_cs[0][i] = 0.f;
    }
    if (i < B*S*DH) {
        g_hd[0][i] = 0.f; g_cd[0][i] = 0.f;
    }
}

__global__ void repack_kernel(
    const float* __restrict__ nWh, const float* __restrict__ nWa, const float* __restrict__ nWb,
    const float* __restrict__ sWh, const float* __restrict__ sWa, const float* __restrict__ sWb,
    const float* __restrict__ dWx, const float* __restrict__ dWh,
    const float* __restrict__ dWa, const float* __restrict__ dWb)
{
    int i = blockIdx.x * blockDim.x + threadIdx.x;
    if (i < 32*256) {
        int kk = i >> 8, c = i & 255;
        int k0 = (2*kk)*256 + c, k1 = k0 + 256;
        pnWh2[i] = make_float2(nWh[k0], nWh[k1]);
        pnWa2[i] = make_float2(nWa[k0], nWa[k1]);
        pnWb2[i] = make_float2(nWb[k0], nWb[k1]);
        psWh2[i] = make_float2(sWh[k0], sWh[k1]);
        psWa2[i] = make_float2(sWa[k0], sWa[k1]);
        psWb2[i] = make_float2(sWb[k0], sWb[k1]);
    }
    if (i < 64*512) {
        int kk = i >> 9, c = i & 511;
        int k0 = (2*kk)*512 + c, k1 = k0 + 512;
        pdWx2[i] = make_float2(dWx[k0], dWx[k1]);
        pdWh2[i] = make_float2(dWh[k0], dWh[k1]);
        pdWa2[i] = make_float2(dWa[k0], dWa[k1]);
        pdWb2[i] = make_float2(dWb[k0], dWb[k1]);
    }
}

__global__ void __launch_bounds__(TPB, 1) step_kernel(
    const float* __restrict__ xg,
    const float* __restrict__ nWx, const float* __restrict__ nb,
    const float* __restrict__ sWx, const float* __restrict__ sb,
    const float* __restrict__ db,
    const float* __restrict__ onW, const float* __restrict__ onb,
    const float* __restrict__ osW, const float* __restrict__ osb,
    float* __restrict__ out, int t)
{
    extern __shared__ float sm[];
    float* hnp = sm + OFF_HNP;
    float* hsp = sm + OFF_HSP;
    float* hdp = sm + OFF_HDP;
    float* hnc = sm + OFF_HNC;
    float* hsc = sm + OFF_HSC;
    float* hdc = sm + OFF_HDC;
    float* gn  = sm + OFF_GN;
    float* gs  = sm + OFF_GS;
    float* gd  = sm + OFF_GD;
    float* xin = sm + OFF_XIN;
    float* o0s = sm + OFF_O0;
    float* o1s = sm + OFF_O1;

    const int tid = threadIdx.x;
    const int bb  = blockIdx.y;
    const int s0  = blockIdx.x * TS;
    const int pp  = t & 1;
    const int qq  = pp ^ 1;

    // ---- load prev-state halos (sites s0-2 .. s0+TS) ----
    for (int i = tid; i < NQ*NH; i += TPB) {
        int q = i >> 6; int sg = s0 - 2 + q;
        bool v = ((unsigned)sg < (unsigned)S);
        int gi = (bb*S + sg) * NH + (i & 63);
        hnp[i] = v ? g_hn[pp][gi] : 0.f;
        hsp[i] = v ? g_hs[pp][gi] : 0.f;
    }
    for (int i = tid; i < NQ*DH; i += TPB) {
        int q = i >> 7; int sg = s0 - 2 + q;
        bool v = ((unsigned)sg < (unsigned)S);
        hdp[i] = v ? g_hd[pp][(bb*S + sg) * DH + (i & 127)] : 0.f;
    }
    for (int i = tid; i < NS*4; i += TPB) {
        int r = i >> 2; int sg = s0 - 1 + r;
        xin[i] = ((unsigned)sg < (unsigned)S)
                 ? xg[(((size_t)bb*T + t)*S + sg)*4 + (i & 3)] : 0.f;
    }
    __syncthreads();

    // ---- n & s gates: 2 site-groups x 256 columns; k packed in pairs ----
    {
        const int h   = tid >> 8;     // site group 0/1
        const int col = tid & 255;
        const int rb  = h * 8;        // group0: sites 0..8, group1: 8..16 (dup @8)
        ull an2[9], as2[9];
        #pragma unroll
        for (int j = 0; j < 9; j++) { an2[j] = 0ULL; as2[j] = 0ULL; }

        #pragma unroll 4
        for (int kk = 0; kk < 32; kk++) {
            ull wh2 = ld2g(pnWh2, kk*256 + col);
            ull wa2 = ld2g(pnWa2, kk*256 + col);
            ull wb2 = ld2g(pnWb2, kk*256 + col);
            ull vh2 = ld2g(psWh2, kk*256 + col);
            ull va2 = ld2g(psWa2, kk*256 + col);
            ull vb2 = ld2g(psWb2, kk*256 + col);
            #pragma unroll
            for (int dq = 0; dq < 11; dq++) {
                ull hn2 = ld2s(&hnp[(rb+dq)*NH + 2*kk]);
                ull hs2 = ld2s(&hsp[(rb+dq)*NH + 2*kk]);
                if (dq >= 1 && dq <= 9) { FMA2(an2[dq-1], hn2, wh2); FMA2(as2[dq-1], hs2, vh2); }
                if (dq >= 2)            { FMA2(an2[dq-2], hn2, wa2); FMA2(as2[dq-2], hs2, va2); }
                if (dq <= 8)            { FMA2(an2[dq],   hn2, wb2); FMA2(as2[dq],   hs2, vb2); }
            }
        }

        float w0 = nWx[col], w1 = nWx[256 + col], w2 = nWx[512 + col];
        float ws = sWx[col];
        float bn_ = nb[col], bs_ = sb[col];
        #pragma unroll
        for (int j = 0; j < 9; j++) {
            const float* xr = &xin[(rb+j)*4];
            float lo, hi;
            UNPACK2(lo, hi, an2[j]);
            gn[(rb+j)*256 + col] = lo + hi + bn_ + xr[0]*w0 + xr[1]*w1 + xr[2]*w2;
            UNPACK2(lo, hi, as2[j]);
            gs[(rb+j)*256 + col] = lo + hi + bs_ + xr[3]*ws;
        }
    }
    __syncthreads();

    // ---- n & s cell updates ----
    for (int i = tid; i < NS*NH; i += TPB) {
        int r = i >> 6, e = i & 63;
        int sg = s0 - 1 + r;
        bool v = ((unsigned)sg < (unsigned)S);
        int gi = v ? (bb*S + sg)*NH + e : 0;
        {
            float ii = gn[r*256 + e],       ff = gn[r*256 + 64 + e];
            float uu = gn[r*256 + 128 + e], oo = gn[r*256 + 192 + e];
            float cp = v ? g_cn[pp][gi] : 0.f;
            float c2 = sigm(ff)*cp + sigm(ii)*tanhf(uu);
            float hh = sigm(oo)*tanhf(c2);
            if (!v) { c2 = 0.f; hh = 0.f; }
            hnc[i] = hh;
            if (r >= 1) { g_cn[qq][gi] = c2; g_hn[qq][gi] = hh; }
        }
        {
            float ii = gs[r*256 + e],       ff = gs[r*256 + 64 + e];
            float uu = gs[r*256 + 128 + e], oo = gs[r*256 + 192 + e];
            float cp = v ? g_cs[pp][gi] : 0.f;
            float c2 = sigm(ff)*cp + sigm(ii)*tanhf(uu);
            float hh = sigm(oo)*tanhf(c2);
            if (!v) { c2 = 0.f; hh = 0.f; }
            hsc[i] = hh;
            if (r >= 1) { g_cs[qq][gi] = c2; g_hs[qq][gi] = hh; }
        }
    }
    __syncthreads();

    // ---- d gates: one column per thread, all 17 sites, k packed ----
    {
        ull a2[17];
        #pragma unroll
        for (int r = 0; r < 17; r++) a2[r] = 0ULL;

        #pragma unroll 2
        for (int kk = 0; kk < 32; kk++) {
            ull w2 = ld2g(pdWx2, kk*512 + tid);
            #pragma unroll
            for (int r = 0; r < 17; r++) {
                ull h2 = ld2s(&hnc[r*NH + 2*kk]);
                FMA2(a2[r], h2, w2);
            }
        }
        #pragma unroll 2
        for (int kk = 0; kk < 32; kk++) {
            ull w2 = ld2g(pdWx2, (32+kk)*512 + tid);
            #pragma unroll
            for (int r = 0; r < 17; r++) {
                ull h2 = ld2s(&hsc[r*NH + 2*kk]);
                FMA2(a2[r], h2, w2);
            }
        }
        #pragma unroll 2
        for (int kk = 0; kk < 64; kk++) {
            ull wh2 = ld2g(pdWh2, kk*512 + tid);
            ull wa2 = ld2g(pdWa2, kk*512 + tid);
            ull wb2 = ld2g(pdWb2, kk*512 + tid);
            #pragma unroll
            for (int q = 0; q < 19; q++) {
                ull h2 = ld2s(&hdp[q*DH + 2*kk]);
                if (q >= 1 && q <= 17) FMA2(a2[q-1], h2, wh2);
                if (q >= 2)            FMA2(a2[q-2], h2, wa2);
                if (q <= 16)           FMA2(a2[q],   h2, wb2);
            }
        }
        float bd = db[tid];
        #pragma unroll
        for (int r = 0; r < 17; r++) {
            float lo, hi;
            UNPACK2(lo, hi, a2[r]);
            gd[r*512 + tid] = lo + hi + bd;
        }
    }
    __syncthreads();

    // ---- d cell update ----
    for (int i = tid; i < NS*DH; i += TPB) {
        int r = i >> 7, e = i & 127;
        int sg = s0 - 1 + r;
        bool v = ((unsigned)sg < (unsigned)S);
        int gi = v ? (bb*S + sg)*DH + e : 0;
        float ii = gd[r*512 + e],       ff = gd[r*512 + 128 + e];
        float uu = gd[r*512 + 256 + e], oo = gd[r*512 + 384 + e];
        float cp = v ? g_cd[pp][gi] : 0.f;
        float c2 = sigm(ff)*cp + sigm(ii)*tanhf(uu);
        float hh = sigm(oo)*tanhf(c2);
        if (!v) { c2 = 0.f; hh = 0.f; }
        hdc[i] = hh;
        if (r >= 1) { g_cd[qq][gi] = c2; g_hd[qq][gi] = hh; }
    }
    __syncthreads();

    // ---- output heads ----
    if (tid < 2*NS) {
        int r = tid % NS;
        int which = tid / NS;
        const float* W = which ? osW : onW;
        float acc = which ? osb[0] : onb[0];
        #pragma unroll 8
        for (int k = 0; k < DH; k++) acc += hdc[r*DH + k] * W[k];
        if (which) o1s[r] = acc; else o0s[r] = acc;
    }
    __syncthreads();

    // ---- assemble next-input record and write output for t >= 20 ----
    if (t >= 20 && tid >= 1 && tid <= TS) {
        int r = tid;
        int sg = s0 + r - 1;
        float o0 = o0s[r];
        float o1 = o1s[r];
        float inflow, spd;
        if (sg == 0) {
            inflow = xg[(((size_t)bb*T + (t+1))*S + 0)*4 + 1];
            spd    = xg[(((size_t)bb*T + (t+1))*S + 0)*4 + 3];
        } else {
            inflow = o0s[r-1];
            spd    = o1;
        }
        float numc = xin[r*4 + 2] + inflow - o0;
        float* o = out + ((((size_t)bb*TOUT) + (t - 20))*S + sg)*4;
        o[0] = o0; o[1] = inflow; o[2] = numc; o[3] = spd;
    }
}

extern "C" void kernel_launch(void* const* d_in, const int* in_sizes, int n_in,
                              void* d_out, int out_size) {
    const float* xg  = (const float*)d_in[0];
    const float* nWx = (const float*)d_in[1];
    const float* nWh = (const float*)d_in[2];
    const float* nWa = (const float*)d_in[3];
    const float* nWb = (const float*)d_in[4];
    const float* nb  = (const float*)d_in[5];
    const float* sWx = (const float*)d_in[6];
    const float* sWh = (const float*)d_in[7];
    const float* sWa = (const float*)d_in[8];
    const float* sWb = (const float*)d_in[9];
    const float* sb  = (const float*)d_in[10];
    const float* dWx = (const float*)d_in[11];
    const float* dWh = (const float*)d_in[12];
    const float* dWa = (const float*)d_in[13];
    const float* dWb = (const float*)d_in[14];
    const float* db  = (const float*)d_in[15];
    const float* onW = (const float*)d_in[16];
    const float* onb = (const float*)d_in[17];
    const float* osW = (const float*)d_in[18];
    const float* osb = (const float*)d_in[19];
    float* out = (float*)d_out;

    (void)in_sizes; (void)n_in; (void)out_size;

    const int smem_bytes = SMEM_FLOATS * (int)sizeof(float);
    cudaFuncSetAttribute(step_kernel,
                         cudaFuncAttributeMaxDynamicSharedMemorySize, smem_bytes);

    init_states_kernel<<<(B*S*DH + 255) / 256, 256>>>();
    repack_kernel<<<(64*512 + 255) / 256, 256>>>(nWh, nWa, nWb, sWh, sWa, sWb,
                                                 dWx, dWh, dWa, dWb);

    dim3 grid(S / TS, B);
    for (int t = 0; t < T - 1; ++t) {
        step_kernel<<<grid, TPB, smem_bytes>>>(
            xg, nWx, nb, sWx, sb, db,
            onW, onb, osW, osb, out, t);
    }
}

// round 4
// speedup vs baseline: 1.7251x; 1.3433x over previous
#include <cuda_runtime.h>
#include <cuda_bf16.h>
#include <math.h>

typedef unsigned long long ull;
typedef unsigned int uint;

#define B  16
#define T  128
#define S  128
#define NH 64
#define DH 128
#define TS 16      // owned sites per block
#define NS 17      // computed sites (own + 1 left-halo site)
#define NQ 19      // prev-state halo sites (s0-2 .. s0+TS)
#define TPB 512
#define TOUT 107   // T-1-20

#define RS_NS 200  // A_n/A_s row stride in bf16 (400B, ≡16 mod 128 -> conflict-free frags)
#define RS_D  520  // A_d row stride in bf16 (1040B, ≡16 mod 128)

// Persistent double-buffered recurrent state
__device__ float g_hn[2][B*S*NH];
__device__ float g_cn[2][B*S*NH];
__device__ float g_hs[2][B*S*NH];
__device__ float g_cs[2][B*S*NH];
__device__ float g_hd[2][B*S*DH];
__device__ float g_cd[2][B*S*DH];

// Fragment-ordered bf16 weight arrays (hi / lo split).
// Index: ((kt*NT + nt)*32 + lane); each ull = {b0(lo32): k0,k0+1 ; b1(hi32): k0+8,k0+9}
__device__ ull fBn_h[12*32*32], fBn_l[12*32*32];
__device__ ull fBs_h[12*32*32], fBs_l[12*32*32];
__device__ ull fBd_h[32*64*32], fBd_l[32*64*32];

// ---- shared memory layout (float granularity) ----
#define OFF_HNP 0                       // 19*64
#define OFF_HSP (OFF_HNP + NQ*NH)       // 19*64
#define OFF_HDP (OFF_HSP + NQ*NH)       // 19*128
#define OFF_HNC (OFF_HDP + NQ*DH)       // 17*64
#define OFF_HSC (OFF_HNC + NS*NH)       // 17*64
#define OFF_HDC (OFF_HSC + NS*NH)       // 17*128
#define OFF_XIN (OFF_HDC + NS*DH)       // 17*4
#define OFF_O0  (OFF_XIN + NS*4)        // 17
#define OFF_O1  (OFF_O0 + NS)           // 17
#define OFF_R1  (((OFF_O1 + NS) + 1) & ~1)  // region1
#define R1_FLOATS 12800                  // max(4*32*200 bf16 = 12800 floats, gd 8704)
#define OFF_R2  (OFF_R1 + R1_FLOATS)     // region2
#define R2_FLOATS 16640                  // max(2*32*520 bf16 = 16640 floats, gn+gs 8704)
#define SMEM_FLOATS (OFF_R2 + R2_FLOATS)

#define MMA4(c, a0,a1,a2,a3, b0,b1) \
  asm volatile("mma.sync.aligned.m16n8k16.row.col.f32.bf16.bf16.f32 " \
    "{%0,%1,%2,%3}, {%4,%5,%6,%7}, {%8,%9}, {%0,%1,%2,%3};" \
    : "+f"(c[0]), "+f"(c[1]), "+f"(c[2]), "+f"(c[3]) \
    : "r"(a0), "r"(a1), "r"(a2), "r"(a3), "r"(b0), "r"(b1))

__device__ __forceinline__ float sigm(float x) { return 1.f / (1.f + __expf(-x)); }

__device__ __forceinline__ uint pack2(__nv_bfloat16 a, __nv_bfloat16 b) {
    __nv_bfloat16_raw ra = *(__nv_bfloat16_raw*)&a;
    __nv_bfloat16_raw rb = *(__nv_bfloat16_raw*)&b;
    return (uint)ra.x | ((uint)rb.x << 16);
}

__device__ __forceinline__ void split_bf16(float v, __nv_bfloat16& h, __nv_bfloat16& l) {
    h = __float2bfloat16_rn(v);
    l = __float2bfloat16_rn(v - __bfloat162float(h));
}

__global__ void init_states_kernel() {
    int i = blockIdx.x * blockDim.x + threadIdx.x;
    if (i < B*S*NH) {
        g_hn[0][i] = 0.f; g_cn[0][i] = 0.f;
        g_hs[0][i] = 0.f; g_cs[0][i] = 0.f;
    }
    if (i < B*S*DH) {
        g_hd[0][i] = 0.f; g_cd[0][i] = 0.f;
    }
}

// Build fragment-ordered hi/lo bf16 weight arrays.
__global__ void repack_kernel(
    const float* __restrict__ nWh, const float* __restrict__ nWa, const float* __restrict__ nWb,
    const float* __restrict__ sWh, const float* __restrict__ sWa, const float* __restrict__ sWb,
    const float* __restrict__ dWx, const float* __restrict__ dWh,
    const float* __restrict__ dWa, const float* __restrict__ dWb)
{
    int idx = blockIdx.x * blockDim.x + threadIdx.x;
    if (idx < 32*64*32) {
        // d combined: K rows 0..127 = dWx, 128..255 = dWh, 256..383 = dWa, 384..511 = dWb
        int lane = idx & 31, nt = (idx >> 5) & 63, kt = idx >> 11;
        int n = nt*8 + (lane >> 2);
        int k0 = kt*16 + (lane & 3)*2;
        float v[4];
        #pragma unroll
        for (int j = 0; j < 4; j++) {
            int kk = k0 + (j >> 1)*8 + (j & 1);
            float x;
            if      (kk < 128) x = dWx[kk*512 + n];
            else if (kk < 256) x = dWh[(kk-128)*512 + n];
            else if (kk < 384) x = dWa[(kk-256)*512 + n];
            else               x = dWb[(kk-384)*512 + n];
            v[j] = x;
        }
        __nv_bfloat16 h[4], l[4];
        #pragma unroll
        for (int j = 0; j < 4; j++) split_bf16(v[j], h[j], l[j]);
        fBd_h[idx] = (ull)pack2(h[0], h[1]) | ((ull)pack2(h[2], h[3]) << 32);
        fBd_l[idx] = (ull)pack2(l[0], l[1]) | ((ull)pack2(l[2], l[3]) << 32);
    }
    int idx2 = idx - 32*64*32;
    if (idx2 >= 0 && idx2 < 2*12*32*32) {
        int set = idx2 / (12*32*32);
        int e = idx2 % (12*32*32);
        int lane = e & 31, nt = (e >> 5) & 31, kt = e >> 10;
        int n = nt*8 + (lane >> 2);
        int k0 = kt*16 + (lane & 3)*2;
        const float* Wh = set ? sWh : nWh;
        const float* Wa = set ? sWa : nWa;
        const float* Wb = set ? sWb : nWb;
        float v[4];
        #pragma unroll
        for (int j = 0; j < 4; j++) {
            int kk = k0 + (j >> 1)*8 + (j & 1);
            float x;
            if      (kk < 64)  x = Wh[kk*256 + n];
            else if (kk < 128) x = Wa[(kk-64)*256 + n];
            else               x = Wb[(kk-128)*256 + n];
            v[j] = x;
        }
        __nv_bfloat16 h[4], l[4];
        #pragma unroll
        for (int j = 0; j < 4; j++) split_bf16(v[j], h[j], l[j]);
        ull* Fh = set ? fBs_h : fBn_h;
        ull* Fl = set ? fBs_l : fBn_l;
        Fh[e] = (ull)pack2(h[0], h[1]) | ((ull)pack2(h[2], h[3]) << 32);
        Fl[e] = (ull)pack2(l[0], l[1]) | ((ull)pack2(l[2], l[3]) << 32);
    }
}

__global__ void __launch_bounds__(TPB, 1) step_kernel(
    const float* __restrict__ xg,
    const float* __restrict__ nWx, const float* __restrict__ nb,
    const float* __restrict__ sWx, const float* __restrict__ sb,
    const float* __restrict__ db,
    const float* __restrict__ onW, const float* __restrict__ onb,
    const float* __restrict__ osW, const float* __restrict__ osb,
    float* __restrict__ out, int t)
{
    extern __shared__ float sm[];
    float* hnp = sm + OFF_HNP;
    float* hsp = sm + OFF_HSP;
    float* hdp = sm + OFF_HDP;
    float* hnc = sm + OFF_HNC;
    float* hsc = sm + OFF_HSC;
    float* hdc = sm + OFF_HDC;
    float* xin = sm + OFF_XIN;
    float* o0s = sm + OFF_O0;
    float* o1s = sm + OFF_O1;

    // region1: A_n/A_s (bf16 hi/lo) overlaid with gd
    __nv_bfloat16* An_h = (__nv_bfloat16*)(sm + OFF_R1);
    __nv_bfloat16* An_l = An_h + 32*RS_NS;
    __nv_bfloat16* As_h = An_l + 32*RS_NS;
    __nv_bfloat16* As_l = As_h + 32*RS_NS;
    float* gd = sm + OFF_R1;
    // region2: A_d (bf16 hi/lo) overlaid with gn+gs
    __nv_bfloat16* Ad_h = (__nv_bfloat16*)(sm + OFF_R2);
    __nv_bfloat16* Ad_l = Ad_h + 32*RS_D;
    float* gn = sm + OFF_R2;
    float* gs = gn + NS*256;

    const int tid = threadIdx.x;
    const int w   = tid >> 5;
    const int lane = tid & 31;
    const int bb  = blockIdx.y;
    const int s0  = blockIdx.x * TS;
    const int pp  = t & 1;
    const int qq  = pp ^ 1;

    // ---- load prev-state halos (sites s0-2 .. s0+TS) ----
    for (int i = tid; i < NQ*NH; i += TPB) {
        int q = i >> 6; int sg = s0 - 2 + q;
        bool v = ((unsigned)sg < (unsigned)S);
        int gi = (bb*S + sg) * NH + (i & 63);
        hnp[i] = v ? g_hn[pp][gi] : 0.f;
        hsp[i] = v ? g_hs[pp][gi] : 0.f;
    }
    for (int i = tid; i < NQ*DH; i += TPB) {
        int q = i >> 7; int sg = s0 - 2 + q;
        bool v = ((unsigned)sg < (unsigned)S);
        hdp[i] = v ? g_hd[pp][(bb*S + sg) * DH + (i & 127)] : 0.f;
    }
    for (int i = tid; i < NS*4; i += TPB) {
        int r = i >> 2; int sg = s0 - 1 + r;
        xin[i] = ((unsigned)sg < (unsigned)S)
                 ? xg[(((size_t)bb*T + t)*S + sg)*4 + (i & 3)] : 0.f;
    }
    __syncthreads();

    // ---- build A_n / A_s: row r = gate site, K = [h(r+1)|h(r+2)|h(r)] ----
    for (int i = tid; i < 32*192; i += TPB) {
        int r = i / 192, k = i - r*192;
        float vn = 0.f, vs = 0.f;
        if (r <= 16) {
            int q, kk;
            if (k < 64)       { q = r + 1; kk = k; }
            else if (k < 128) { q = r + 2; kk = k - 64; }
            else              { q = r;     kk = k - 128; }
            vn = hnp[q*NH + kk];
            vs = hsp[q*NH + kk];
        }
        __nv_bfloat16 h, l;
        split_bf16(vn, h, l);
        An_h[r*RS_NS + k] = h; An_l[r*RS_NS + k] = l;
        split_bf16(vs, h, l);
        As_h[r*RS_NS + k] = h; As_l[r*RS_NS + k] = l;
    }
    __syncthreads();

    // ---- n & s gate GEMM via mma.sync (bf16 3-term split) ----
    {
        const int set   = w >> 3;       // 0:n, 1:s
        const int mtile = (w >> 2) & 1;
        const int ngrp  = w & 3;
        const __nv_bfloat16* Ah = set ? As_h : An_h;
        const __nv_bfloat16* Al = set ? As_l : An_l;
        const ull* Fh = set ? fBs_h : fBn_h;
        const ull* Fl = set ? fBs_l : fBn_l;

        float acc[8][4];
        #pragma unroll
        for (int j = 0; j < 8; j++)
            #pragma unroll
            for (int c = 0; c < 4; c++) acc[j][c] = 0.f;

        const int row = mtile*16 + (lane >> 2);
        const int kb  = (lane & 3)*2;
        for (int kt = 0; kt < 12; kt++) {
            const __nv_bfloat16* pA = Ah + row*RS_NS + kt*16 + kb;
            uint ah0 = *(const uint*)pA;
            uint ah1 = *(const uint*)(pA + 8*RS_NS);
            uint ah2 = *(const uint*)(pA + 8);
            uint ah3 = *(const uint*)(pA + 8*RS_NS + 8);
            const __nv_bfloat16* qA = Al + row*RS_NS + kt*16 + kb;
            uint al0 = *(const uint*)qA;
            uint al1 = *(const uint*)(qA + 8*RS_NS);
            uint al2 = *(const uint*)(qA + 8);
            uint al3 = *(const uint*)(qA + 8*RS_NS + 8);
            #pragma unroll
            for (int j = 0; j < 8; j++) {
                int nt = ngrp*8 + j;
                ull bh = Fh[(kt*32 + nt)*32 + lane];
                ull bl = Fl[(kt*32 + nt)*32 + lane];
                uint bh0 = (uint)bh, bh1 = (uint)(bh >> 32);
                uint bl0 = (uint)bl, bl1 = (uint)(bl >> 32);
                MMA4(acc[j], ah0, ah1, ah2, ah3, bh0, bh1);
                MMA4(acc[j], ah0, ah1, ah2, ah3, bl0, bl1);
                MMA4(acc[j], al0, al1, al2, al3, bh0, bh1);
            }
        }
        float* g = set ? gs : gn;
        const int site0 = mtile*16 + (lane >> 2);
        const int col   = (lane & 3)*2;
        #pragma unroll
        for (int j = 0; j < 8; j++) {
            int c0 = (ngrp*8 + j)*8 + col;
            if (site0 < NS)
                *(float2*)&g[site0*256 + c0] = make_float2(acc[j][0], acc[j][1]);
            if (site0 + 8 < NS)
                *(float2*)&g[(site0+8)*256 + c0] = make_float2(acc[j][2], acc[j][3]);
        }
    }
    __syncthreads();

    // ---- n & s cell updates (x-input + bias folded here in exact fp32) ----
    for (int i = tid; i < NS*NH; i += TPB) {
        int r = i >> 6, e = i & 63;
        int sg = s0 - 1 + r;
        bool v = ((unsigned)sg < (unsigned)S);
        int gi = v ? (bb*S + sg)*NH + e : 0;
        float xr0 = xin[r*4+0], xr1 = xin[r*4+1], xr2 = xin[r*4+2], xr3 = xin[r*4+3];
        // n cell
        {
            float ii = gn[r*256 + e]      + nb[e]      + xr0*nWx[e]      + xr1*nWx[256+e]  + xr2*nWx[512+e];
            float ff = gn[r*256 + 64+e]   + nb[64+e]   + xr0*nWx[64+e]   + xr1*nWx[320+e]  + xr2*nWx[576+e];
            float uu = gn[r*256 + 128+e]  + nb[128+e]  + xr0*nWx[128+e]  + xr1*nWx[384+e]  + xr2*nWx[640+e];
            float oo = gn[r*256 + 192+e]  + nb[192+e]  + xr0*nWx[192+e]  + xr1*nWx[448+e]  + xr2*nWx[704+e];
            float cp = v ? g_cn[pp][gi] : 0.f;
            float c2 = sigm(ff)*cp + sigm(ii)*tanhf(uu);
            float hh = sigm(oo)*tanhf(c2);
            if (!v) { c2 = 0.f; hh = 0.f; }
            hnc[i] = hh;
            if (r >= 1) { g_cn[qq][gi] = c2; g_hn[qq][gi] = hh; }
        }
        // s cell
        {
            float ii = gs[r*256 + e]      + sb[e]      + xr3*sWx[e];
            float ff = gs[r*256 + 64+e]   + sb[64+e]   + xr3*sWx[64+e];
            float uu = gs[r*256 + 128+e]  + sb[128+e]  + xr3*sWx[128+e];
            float oo = gs[r*256 + 192+e]  + sb[192+e]  + xr3*sWx[192+e];
            float cp = v ? g_cs[pp][gi] : 0.f;
            float c2 = sigm(ff)*cp + sigm(ii)*tanhf(uu);
            float hh = sigm(oo)*tanhf(c2);
            if (!v) { c2 = 0.f; hh = 0.f; }
            hsc[i] = hh;
            if (r >= 1) { g_cs[qq][gi] = c2; g_hs[qq][gi] = hh; }
        }
    }
    __syncthreads();

    // ---- build A_d: K = [hnc | hsc | hd(r+1) | hd(r+2) | hd(r)] ----
    for (int i = tid; i < 32*512; i += TPB) {
        int r = i >> 9, k = i & 511;
        float v = 0.f;
        if (r <= 16) {
            if      (k < 64)  v = hnc[r*NH + k];
            else if (k < 128) v = hsc[r*NH + (k-64)];
            else if (k < 256) v = hdp[(r+1)*DH + (k-128)];
            else if (k < 384) v = hdp[(r+2)*DH + (k-256)];
            else              v = hdp[r*DH + (k-384)];
        }
        __nv_bfloat16 h, l;
        split_bf16(v, h, l);
        Ad_h[r*RS_D + k] = h;
        Ad_l[r*RS_D + k] = l;
    }
    __syncthreads();

    // ---- d gate GEMM via mma.sync ----
    {
        const int mtile = w & 1;
        const int ngrp  = w >> 1;    // 0..7
        float acc[8][4];
        #pragma unroll
        for (int j = 0; j < 8; j++)
            #pragma unroll
            for (int c = 0; c < 4; c++) acc[j][c] = 0.f;

        const int row = mtile*16 + (lane >> 2);
        const int kb  = (lane & 3)*2;
        for (int kt = 0; kt < 32; kt++) {
            const __nv_bfloat16* pA = Ad_h + row*RS_D + kt*16 + kb;
            uint ah0 = *(const uint*)pA;
            uint ah1 = *(const uint*)(pA + 8*RS_D);
            uint ah2 = *(const uint*)(pA + 8);
            uint ah3 = *(const uint*)(pA + 8*RS_D + 8);
            const __nv_bfloat16* qA = Ad_l + row*RS_D + kt*16 + kb;
            uint al0 = *(const uint*)qA;
            uint al1 = *(const uint*)(qA + 8*RS_D);
            uint al2 = *(const uint*)(qA + 8);
            uint al3 = *(const uint*)(qA + 8*RS_D + 8);
            #pragma unroll
            for (int j = 0; j < 8; j++) {
                int nt = ngrp*8 + j;
                ull bh = fBd_h[(kt*64 + nt)*32 + lane];
                ull bl = fBd_l[(kt*64 + nt)*32 + lane];
                uint bh0 = (uint)bh, bh1 = (uint)(bh >> 32);
                uint bl0 = (uint)bl, bl1 = (uint)(bl >> 32);
                MMA4(acc[j], ah0, ah1, ah2, ah3, bh0, bh1);
                MMA4(acc[j], ah0, ah1, ah2, ah3, bl0, bl1);
                MMA4(acc[j], al0, al1, al2, al3, bh0, bh1);
            }
        }
        const int site0 = mtile*16 + (lane >> 2);
        const int col   = (lane & 3)*2;
        #pragma unroll
        for (int j = 0; j < 8; j++) {
            int c0 = (ngrp*8 + j)*8 + col;
            if (site0 < NS)
                *(float2*)&gd[site0*512 + c0] = make_float2(acc[j][0], acc[j][1]);
            if (site0 + 8 < NS)
                *(float2*)&gd[(site0+8)*512 + c0] = make_float2(acc[j][2], acc[j][3]);
        }
    }
    __syncthreads();

    // ---- d cell update (+bias fold) ----
    for (int i = tid; i < NS*DH; i += TPB) {
        int r = i >> 7, e = i & 127;
        int sg = s0 - 1 + r;
        bool v = ((unsigned)sg < (unsigned)S);
        int gi = v ? (bb*S + sg)*DH + e : 0;
        float ii = gd[r*512 + e]       + db[e];
        float ff = gd[r*512 + 128 + e] + db[128+e];
        float uu = gd[r*512 + 256 + e] + db[256+e];
        float oo = gd[r*512 + 384 + e] + db[384+e];
        float cp = v ? g_cd[pp][gi] : 0.f;
        float c2 = sigm(ff)*cp + sigm(ii)*tanhf(uu);
        float hh = sigm(oo)*tanhf(c2);
        if (!v) { c2 = 0.f; hh = 0.f; }
        hdc[i] = hh;
        if (r >= 1) { g_cd[qq][gi] = c2; g_hd[qq][gi] = hh; }
    }
    __syncthreads();

    // ---- output heads ----
    if (tid < 2*NS) {
        int r = tid % NS;
        int which = tid / NS;
        const float* W = which ? osW : onW;
        float acc = which ? osb[0] : onb[0];
        #pragma unroll 8
        for (int k = 0; k < DH; k++) acc += hdc[r*DH + k] * W[k];
        if (which) o1s[r] = acc; else o0s[r] = acc;
    }
    __syncthreads();

    // ---- assemble next-input record and write output for t >= 20 ----
    if (t >= 20 && tid >= 1 && tid <= TS) {
        int r = tid;
        int sg = s0 + r - 1;
        float o0 = o0s[r];
        float o1 = o1s[r];
        float inflow, spd;
        if (sg == 0) {
            inflow = xg[(((size_t)bb*T + (t+1))*S + 0)*4 + 1];
            spd    = xg[(((size_t)bb*T + (t+1))*S + 0)*4 + 3];
        } else {
            inflow = o0s[r-1];
            spd    = o1;
        }
        float numc = xin[r*4 + 2] + inflow - o0;
        float* o = out + ((((size_t)bb*TOUT) + (t - 20))*S + sg)*4;
        o[0] = o0; o[1] = inflow; o[2] = numc; o[3] = spd;
    }
}

extern "C" void kernel_launch(void* const* d_in, const int* in_sizes, int n_in,
                              void* d_out, int out_size) {
    const float* xg  = (const float*)d_in[0];
    const float* nWx = (const float*)d_in[1];
    const float* nWh = (const float*)d_in[2];
    const float* nWa = (const float*)d_in[3];
    const float* nWb = (const float*)d_in[4];
    const float* nb  = (const float*)d_in[5];
    const float* sWx = (const float*)d_in[6];
    const float* sWh = (const float*)d_in[7];
    const float* sWa = (const float*)d_in[8];
    const float* sWb = (const float*)d_in[9];
    const float* sb  = (const float*)d_in[10];
    const float* dWx = (const float*)d_in[11];
    const float* dWh = (const float*)d_in[12];
    const float* dWa = (const float*)d_in[13];
    const float* dWb = (const float*)d_in[14];
    const float* db  = (const float*)d_in[15];
    const float* onW = (const float*)d_in[16];
    const float* onb = (const float*)d_in[17];
    const float* osW = (const float*)d_in[18];
    const float* osb = (const float*)d_in[19];
    float* out = (float*)d_out;

    (void)in_sizes; (void)n_in; (void)out_size;

    const int smem_bytes = SMEM_FLOATS * (int)sizeof(float);
    cudaFuncSetAttribute(step_kernel,
                         cudaFuncAttributeMaxDynamicSharedMemorySize, smem_bytes);

    init_states_kernel<<<(B*S*DH + 255) / 256, 256>>>();
    int repack_threads = 32*64*32 + 2*12*32*32;
    repack_kernel<<<(repack_threads + 255) / 256, 256>>>(
        nWh, nWa, nWb, sWh, sWa, sWb, dWx, dWh, dWa, dWb);

    dim3 grid(S / TS, B);
    for (int t = 0; t < T - 1; ++t) {
        step_kernel<<<grid, TPB, smem_bytes>>>(
            xg, nWx, nb, sWx, sb, db,
            onW, onb, osW, osb, out, t);
    }
}

// round 5
// speedup vs baseline: 2.8733x; 1.6656x over previous
#include <cuda_runtime.h>
#include <cuda_bf16.h>
#include <math.h>

typedef unsigned long long ull;
typedef unsigned int uint;

#define B  16
#define T  128
#define S  128
#define NH 64
#define DH 128
#define TS 15      // owned sites per block
#define NS 16      // computed sites (1 halo + 15 owned) -> exactly one m16 tile
#define NQ 18      // prev-state halo rows (s0-2 .. s0+15)
#define NTILE 9    // ceil(128/15)
#define TPB 512
#define TOUT 107   // T-1-20

// Persistent double-buffered recurrent state
__device__ float g_hn[2][B*S*NH];
__device__ float g_cn[2][B*S*NH];
__device__ float g_hs[2][B*S*NH];
__device__ float g_cs[2][B*S*NH];
__device__ float g_hd[2][B*S*DH];
__device__ float g_cd[2][B*S*DH];

// Fragment-ordered interleaved weights: entry (kt,nt,lane) = {bh0,bh1,bl0,bl1}
__device__ uint4 fBn[12*32*32];
__device__ uint4 fBs[12*32*32];
__device__ uint4 fBd[32*64*32];

// ---- shared memory layout (floats; all offsets 16B aligned) ----
#define OFF_HNP 0                        // 18*64
#define OFF_HSP (OFF_HNP + NQ*NH)        // 18*64
#define OFF_HDP (OFF_HSP + NQ*NH)        // 18*128
#define OFF_HNC (OFF_HDP + NQ*DH)        // 16*64
#define OFF_HSC (OFF_HNC + NS*NH)        // 16*64
#define OFF_HDC (OFF_HSC + NS*NH)        // 16*128
#define OFF_XIN (OFF_HDC + NS*DH)        // 16*4
#define OFF_O0  (OFF_XIN + NS*4)         // 16
#define OFF_O1  (OFF_O0 + NS)            // 16
#define OFF_R1  (OFF_O1 + NS)            // ns A frags (6144) / gd (8192) overlay
#define OFF_R2  (OFF_R1 + 8192)          // gn + gs (2*4096)
#define OFF_R3  (OFF_R2 + 8192)          // A_d frags hi+lo (2*4096)
#define SMEM_FLOATS (OFF_R3 + 8192)

#define MMA4(c, a0,a1,a2,a3, b0,b1) \
  asm volatile("mma.sync.aligned.m16n8k16.row.col.f32.bf16.bf16.f32 " \
    "{%0,%1,%2,%3}, {%4,%5,%6,%7}, {%8,%9}, {%0,%1,%2,%3};" \
    : "+f"(c[0]), "+f"(c[1]), "+f"(c[2]), "+f"(c[3]) \
    : "r"(a0), "r"(a1), "r"(a2), "r"(a3), "r"(b0), "r"(b1))

__device__ __forceinline__ float sigm(float x) { return 1.f / (1.f + __expf(-x)); }

__device__ __forceinline__ uint pack2(__nv_bfloat16 a, __nv_bfloat16 b) {
    __nv_bfloat16_raw ra = *(__nv_bfloat16_raw*)&a;
    __nv_bfloat16_raw rb = *(__nv_bfloat16_raw*)&b;
    return (uint)ra.x | ((uint)rb.x << 16);
}

__device__ __forceinline__ void split_bf16(float v, __nv_bfloat16& h, __nv_bfloat16& l) {
    h = __float2bfloat16_rn(v);
    l = __float2bfloat16_rn(v - __bfloat162float(h));
}

// pack hi/lo pairs of two floats into two uints
__device__ __forceinline__ void split_pair(float v0, float v1, uint& hi, uint& lo) {
    __nv_bfloat16 h0, l0, h1, l1;
    split_bf16(v0, h0, l0);
    split_bf16(v1, h1, l1);
    hi = pack2(h0, h1);
    lo = pack2(l0, l1);
}

__global__ void init_states_kernel() {
    int i = blockIdx.x * blockDim.x + threadIdx.x;
    if (i < B*S*NH) {
        g_hn[0][i] = 0.f; g_cn[0][i] = 0.f;
        g_hs[0][i] = 0.f; g_cs[0][i] = 0.f;
    }
    if (i < B*S*DH) {
        g_hd[0][i] = 0.f; g_cd[0][i] = 0.f;
    }
}

__global__ void repack_kernel(
    const float* __restrict__ nWh, const float* __restrict__ nWa, const float* __restrict__ nWb,
    const float* __restrict__ sWh, const float* __restrict__ sWa, const float* __restrict__ sWb,
    const float* __restrict__ dWx, const float* __restrict__ dWh,
    const float* __restrict__ dWa, const float* __restrict__ dWb)
{
    int idx = blockIdx.x * blockDim.x + threadIdx.x;
    if (idx < 32*64*32) {
        int lane = idx & 31, nt = (idx >> 5) & 63, kt = idx >> 11;
        int n = nt*8 + (lane >> 2);
        int k0 = kt*16 + (lane & 3)*2;
        float v[4];
        #pragma unroll
        for (int j = 0; j < 4; j++) {
            int kk = k0 + (j >> 1)*8 + (j & 1);
            float x;
            if      (kk < 128) x = dWx[kk*512 + n];
            else if (kk < 256) x = dWh[(kk-128)*512 + n];
            else if (kk < 384) x = dWa[(kk-256)*512 + n];
            else               x = dWb[(kk-384)*512 + n];
            v[j] = x;
        }
        uint h01, l01, h23, l23;
        split_pair(v[0], v[1], h01, l01);
        split_pair(v[2], v[3], h23, l23);
        fBd[idx] = make_uint4(h01, h23, l01, l23);
    }
    int idx2 = idx - 32*64*32;
    if (idx2 >= 0 && idx2 < 2*12*32*32) {
        int set = idx2 / (12*32*32);
        int e = idx2 % (12*32*32);
        int lane = e & 31, nt = (e >> 5) & 31, kt = e >> 10;
        int n = nt*8 + (lane >> 2);
        int k0 = kt*16 + (lane & 3)*2;
        const float* Wh = set ? sWh : nWh;
        const float* Wa = set ? sWa : nWa;
        const float* Wb = set ? sWb : nWb;
        float v[4];
        #pragma unroll
        for (int j = 0; j < 4; j++) {
            int kk = k0 + (j >> 1)*8 + (j & 1);
            float x;
            if      (kk < 64)  x = Wh[kk*256 + n];
            else if (kk < 128) x = Wa[(kk-64)*256 + n];
            else               x = Wb[(kk-128)*256 + n];
            v[j] = x;
        }
        uint h01, l01, h23, l23;
        split_pair(v[0], v[1], h01, l01);
        split_pair(v[2], v[3], h23, l23);
        (set ? fBs : fBn)[e] = make_uint4(h01, h23, l01, l23);
    }
}

__device__ __forceinline__ float ns_elem(const float* hp, int r, int k) {
    int q, kk;
    if (k < 64)       { q = r + 1; kk = k; }
    else if (k < 128) { q = r + 2; kk = k - 64; }
    else              { q = r;     kk = k - 128; }
    return hp[q*NH + kk];
}

__global__ void __launch_bounds__(TPB, 1) step_kernel(
    const float* __restrict__ xg,
    const float* __restrict__ nWx, const float* __restrict__ nb,
    const float* __restrict__ sWx, const float* __restrict__ sb,
    const float* __restrict__ db,
    const float* __restrict__ onW, const float* __restrict__ onb,
    const float* __restrict__ osW, const float* __restrict__ osb,
    float* __restrict__ out, int t)
{
    extern __shared__ float sm[];
    float* hnp = sm + OFF_HNP;
    float* hsp = sm + OFF_HSP;
    float* hdp = sm + OFF_HDP;
    float* hnc = sm + OFF_HNC;
    float* hsc = sm + OFF_HSC;
    float* hdc = sm + OFF_HDC;
    float* xin = sm + OFF_XIN;
    float* o0s = sm + OFF_O0;
    float* o1s = sm + OFF_O1;

    // region1: ns A frags (uint view) overlaid with gd
    uint* nsFu = (uint*)(sm + OFF_R1);       // An_h@0, An_l@1536, As_h@3072, As_l@4608 (uints)
    uint4* nsF4 = (uint4*)(sm + OFF_R1);     // same, uint4 units of 384 per array
    float* gd = sm + OFF_R1;                 // 16*512
    // region2: gates gn, gs
    float* gn = sm + OFF_R2;                 // 16*256
    float* gs = gn + NS*256;
    // region3: A_d frags
    uint* AdFu = (uint*)(sm + OFF_R3);       // Ad_h@0, Ad_l@4096 (uints)
    uint4* AdF4 = (uint4*)(sm + OFF_R3);     // Ad_h: 1024 uint4, Ad_l: +1024

    const int tid = threadIdx.x;
    const int w    = tid >> 5;
    const int lane = tid & 31;
    const int bb  = blockIdx.y;
    const int s0  = blockIdx.x * TS;
    const int pp  = t & 1;
    const int qq  = pp ^ 1;

    // ---- load prev-state halos (sites s0-2 .. s0+15) ----
    for (int i = tid; i < NQ*NH; i += TPB) {
        int q = i >> 6; int sg = s0 - 2 + q;
        bool v = ((unsigned)sg < (unsigned)S);
        int gi = (bb*S + sg) * NH + (i & 63);
        hnp[i] = v ? g_hn[pp][gi] : 0.f;
        hsp[i] = v ? g_hs[pp][gi] : 0.f;
    }
    for (int i = tid; i < NQ*DH; i += TPB) {
        int q = i >> 7; int sg = s0 - 2 + q;
        bool v = ((unsigned)sg < (unsigned)S);
        hdp[i] = v ? g_hd[pp][(bb*S + sg) * DH + (i & 127)] : 0.f;
    }
    for (int i = tid; i < NS*4; i += TPB) {
        int r = i >> 2; int sg = s0 - 1 + r;
        xin[i] = ((unsigned)sg < (unsigned)S)
                 ? xg[(((size_t)bb*T + t)*S + sg)*4 + (i & 3)] : 0.f;
    }
    __syncthreads();

    // ---- build ns A fragments + prebuild A_d halo fragments (k>=128) ----
    // unit = (kt, lane, reg): element pair at row r, cols k,k+1
    for (int u = tid; u < 12*32*4; u += TPB) {
        int kt = u >> 7, rem = u & 127, ln = rem >> 2, reg = rem & 3;
        int r = (ln >> 2) | ((reg & 1) << 3);
        int k = kt*16 + ((ln & 3) << 1) + ((reg >> 1) << 3);
        uint hi, lo;
        split_pair(ns_elem(hnp, r, k), ns_elem(hnp, r, k+1), hi, lo);
        int base = (kt*32 + ln)*4 + reg;
        nsFu[base] = hi; nsFu[1536 + base] = lo;
        split_pair(ns_elem(hsp, r, k), ns_elem(hsp, r, k+1), hi, lo);
        nsFu[3072 + base] = hi; nsFu[4608 + base] = lo;
    }
    // A_d k in [128,512): kt 8..31
    for (int u = tid; u < 24*32*4; u += TPB) {
        int kt = 8 + (u >> 7), rem = u & 127, ln = rem >> 2, reg = rem & 3;
        int r = (ln >> 2) | ((reg & 1) << 3);
        int k = kt*16 + ((ln & 3) << 1) + ((reg >> 1) << 3);
        float v0, v1;
        if (k < 256)      { v0 = hdp[(r+1)*DH + (k-128)]; v1 = hdp[(r+1)*DH + (k-127)]; }
        else if (k < 384) { v0 = hdp[(r+2)*DH + (k-256)]; v1 = hdp[(r+2)*DH + (k-255)]; }
        else              { v0 = hdp[r*DH + (k-384)];     v1 = hdp[r*DH + (k-383)]; }
        uint hi, lo;
        split_pair(v0, v1, hi, lo);
        int base = (kt*32 + ln)*4 + reg;
        AdFu[base] = hi; AdFu[4096 + base] = lo;
    }
    __syncthreads();

    // ---- ns gate GEMM: 16 warps = 2 sets x 8 col-groups ----
    {
        const int set = w >> 3, grp = w & 7;
        const uint4* Ah4 = nsF4 + set*768;
        const uint4* Al4 = Ah4 + 384;
        const uint4* Bf = set ? fBs : fBn;
        float acc[4][4];
        #pragma unroll
        for (int j = 0; j < 4; j++)
            #pragma unroll
            for (int c = 0; c < 4; c++) acc[j][c] = 0.f;

        for (int kt = 0; kt < 12; kt++) {
            uint4 ah = Ah4[kt*32 + lane];
            uint4 al = Al4[kt*32 + lane];
            #pragma unroll
            for (int j = 0; j < 4; j++) {
                int nt = grp*4 + j;
                uint4 bv = __ldg(&Bf[(kt*32 + nt)*32 + lane]);
                MMA4(acc[j], ah.x, ah.y, ah.z, ah.w, bv.x, bv.y);
                MMA4(acc[j], ah.x, ah.y, ah.z, ah.w, bv.z, bv.w);
                MMA4(acc[j], al.x, al.y, al.z, al.w, bv.x, bv.y);
            }
        }
        float* g = set ? gs : gn;
        int site0 = lane >> 2, cb = (lane & 3)*2;
        #pragma unroll
        for (int j = 0; j < 4; j++) {
            int c0 = (grp*4 + j)*8 + cb;
            *(float2*)&g[site0*256 + c0]     = make_float2(acc[j][0], acc[j][1]);
            *(float2*)&g[(site0+8)*256 + c0] = make_float2(acc[j][2], acc[j][3]);
        }
    }
    __syncthreads();

    // ---- n & s cell updates (x-input + bias folded in exact fp32) ----
    for (int i = tid; i < NS*NH; i += TPB) {
        int r = i >> 6, e = i & 63;
        int sg = s0 - 1 + r;
        bool v = ((unsigned)sg < (unsigned)S);
        int gi = v ? (bb*S + sg)*NH + e : 0;
        float xr0 = xin[r*4+0], xr1 = xin[r*4+1], xr2 = xin[r*4+2], xr3 = xin[r*4+3];
        {
            float ii = gn[r*256 + e]      + nb[e]      + xr0*nWx[e]      + xr1*nWx[256+e]  + xr2*nWx[512+e];
            float ff = gn[r*256 + 64+e]   + nb[64+e]   + xr0*nWx[64+e]   + xr1*nWx[320+e]  + xr2*nWx[576+e];
            float uu = gn[r*256 + 128+e]  + nb[128+e]  + xr0*nWx[128+e]  + xr1*nWx[384+e]  + xr2*nWx[640+e];
            float oo = gn[r*256 + 192+e]  + nb[192+e]  + xr0*nWx[192+e]  + xr1*nWx[448+e]  + xr2*nWx[704+e];
            float cp = v ? g_cn[pp][gi] : 0.f;
            float c2 = sigm(ff)*cp + sigm(ii)*tanhf(uu);
            float hh = sigm(oo)*tanhf(c2);
            if (!v) { c2 = 0.f; hh = 0.f; }
            hnc[i] = hh;
            if (r >= 1 && v) { g_cn[qq][gi] = c2; g_hn[qq][gi] = hh; }
        }
        {
            float ii = gs[r*256 + e]      + sb[e]      + xr3*sWx[e];
            float ff = gs[r*256 + 64+e]   + sb[64+e]   + xr3*sWx[64+e];
            float uu = gs[r*256 + 128+e]  + sb[128+e]  + xr3*sWx[128+e];
            float oo = gs[r*256 + 192+e]  + sb[192+e]  + xr3*sWx[192+e];
            float cp = v ? g_cs[pp][gi] : 0.f;
            float c2 = sigm(ff)*cp + sigm(ii)*tanhf(uu);
            float hh = sigm(oo)*tanhf(c2);
            if (!v) { c2 = 0.f; hh = 0.f; }
            hsc[i] = hh;
            if (r >= 1 && v) { g_cs[qq][gi] = c2; g_hs[qq][gi] = hh; }
        }
    }
    __syncthreads();

    // ---- finish A_d fragments (k < 128: hnc | hsc) ----
    for (int u = tid; u < 8*32*4; u += TPB) {
        int kt = u >> 7, rem = u & 127, ln = rem >> 2, reg = rem & 3;
        int r = (ln >> 2) | ((reg & 1) << 3);
        int k = kt*16 + ((ln & 3) << 1) + ((reg >> 1) << 3);
        float v0, v1;
        if (k < 64) { v0 = hnc[r*NH + k];        v1 = hnc[r*NH + k + 1]; }
        else        { v0 = hsc[r*NH + (k-64)];   v1 = hsc[r*NH + (k-63)]; }
        uint hi, lo;
        split_pair(v0, v1, hi, lo);
        int base = (kt*32 + ln)*4 + reg;
        AdFu[base] = hi; AdFu[4096 + base] = lo;
    }
    __syncthreads();

    // ---- d gate GEMM: 16 warps x 4 n-tiles each ----
    {
        float acc[4][4];
        #pragma unroll
        for (int j = 0; j < 4; j++)
            #pragma unroll
            for (int c = 0; c < 4; c++) acc[j][c] = 0.f;

        for (int kt = 0; kt < 32; kt++) {
            uint4 ah = AdF4[kt*32 + lane];
            uint4 al = AdF4[1024 + kt*32 + lane];
            #pragma unroll
            for (int j = 0; j < 4; j++) {
                int nt = w*4 + j;
                uint4 bv = __ldg(&fBd[(kt*64 + nt)*32 + lane]);
                MMA4(acc[j], ah.x, ah.y, ah.z, ah.w, bv.x, bv.y);
                MMA4(acc[j], ah.x, ah.y, ah.z, ah.w, bv.z, bv.w);
                MMA4(acc[j], al.x, al.y, al.z, al.w, bv.x, bv.y);
            }
        }
        int site0 = lane >> 2, cb = (lane & 3)*2;
        #pragma unroll
        for (int j = 0; j < 4; j++) {
            int c0 = (w*4 + j)*8 + cb;
            *(float2*)&gd[site0*512 + c0]     = make_float2(acc[j][0], acc[j][1]);
            *(float2*)&gd[(site0+8)*512 + c0] = make_float2(acc[j][2], acc[j][3]);
        }
    }
    __syncthreads();

    // ---- d cell update (+bias fold) ----
    for (int i = tid; i < NS*DH; i += TPB) {
        int r = i >> 7, e = i & 127;
        int sg = s0 - 1 + r;
        bool v = ((unsigned)sg < (unsigned)S);
        int gi = v ? (bb*S + sg)*DH + e : 0;
        float ii = gd[r*512 + e]       + db[e];
        float ff = gd[r*512 + 128 + e] + db[128+e];
        float uu = gd[r*512 + 256 + e] + db[256+e];
        float oo = gd[r*512 + 384 + e] + db[384+e];
        float cp = v ? g_cd[pp][gi] : 0.f;
        float c2 = sigm(ff)*cp + sigm(ii)*tanhf(uu);
        float hh = sigm(oo)*tanhf(c2);
        if (!v) { c2 = 0.f; hh = 0.f; }
        hdc[i] = hh;
        if (r >= 1 && v) { g_cd[qq][gi] = c2; g_hd[qq][gi] = hh; }
    }
    __syncthreads();

    // ---- output heads ----
    if (tid < 2*NS) {
        int r = tid & 15;
        int which = tid >> 4;
        const float* W = which ? osW : onW;
        float acc = which ? osb[0] : onb[0];
        #pragma unroll 8
        for (int k = 0; k < DH; k++) acc += hdc[r*DH + k] * W[k];
        if (which) o1s[r] = acc; else o0s[r] = acc;
    }
    __syncthreads();

    // ---- assemble next-input record and write output for t >= 20 ----
    if (t >= 20 && tid >= 1 && tid <= TS) {
        int r = tid;
        int sg = s0 + r - 1;
        if (sg < S) {
            float o0 = o0s[r];
            float o1 = o1s[r];
            float inflow, spd;
            if (sg == 0) {
                inflow = xg[(((size_t)bb*T + (t+1))*S + 0)*4 + 1];
                spd    = xg[(((size_t)bb*T + (t+1))*S + 0)*4 + 3];
            } else {
                inflow = o0s[r-1];
                spd    = o1;
            }
            float numc = xin[r*4 + 2] + inflow - o0;
            float* o = out + ((((size_t)bb*TOUT) + (t - 20))*S + sg)*4;
            o[0] = o0; o[1] = inflow; o[2] = numc; o[3] = spd;
        }
    }
}

extern "C" void kernel_launch(void* const* d_in, const int* in_sizes, int n_in,
                              void* d_out, int out_size) {
    const float* xg  = (const float*)d_in[0];
    const float* nWx = (const float*)d_in[1];
    const float* nWh = (const float*)d_in[2];
    const float* nWa = (const float*)d_in[3];
    const float* nWb = (const float*)d_in[4];
    const float* nb  = (const float*)d_in[5];
    const float* sWx = (const float*)d_in[6];
    const float* sWh = (const float*)d_in[7];
    const float* sWa = (const float*)d_in[8];
    const float* sWb = (const float*)d_in[9];
    const float* sb  = (const float*)d_in[10];
    const float* dWx = (const float*)d_in[11];
    const float* dWh = (const float*)d_in[12];
    const float* dWa = (const float*)d_in[13];
    const float* dWb = (const float*)d_in[14];
    const float* db  = (const float*)d_in[15];
    const float* onW = (const float*)d_in[16];
    const float* onb = (const float*)d_in[17];
    const float* osW = (const float*)d_in[18];
    const float* osb = (const float*)d_in[19];
    float* out = (float*)d_out;

    (void)in_sizes; (void)n_in; (void)out_size;

    const int smem_bytes = SMEM_FLOATS * (int)sizeof(float);
    cudaFuncSetAttribute(step_kernel,
                         cudaFuncAttributeMaxDynamicSharedMemorySize, smem_bytes);

    init_states_kernel<<<(B*S*DH + 255) / 256, 256>>>();
    int repack_threads = 32*64*32 + 2*12*32*32;
    repack_kernel<<<(repack_threads + 255) / 256, 256>>>(
        nWh, nWa, nWb, sWh, sWa, sWb, dWx, dWh, dWa, dWb);

    dim3 grid(NTILE, B);
    for (int t = 0; t < T - 1; ++t) {
        step_kernel<<<grid, TPB, smem_bytes>>>(
            xg, nWx, nb, sWx, sb, db,
            onW, onb, osW, osb, out, t);
    }
}

// round 6
// speedup vs baseline: 4.6644x; 1.6233x over previous
#include <cuda_runtime.h>
#include <cuda_bf16.h>
#include <math.h>

typedef unsigned long long ull;
typedef unsigned int uint;

#define B  16
#define T  128
#define S  128
#define NH 64
#define DH 128
#define TS 15      // owned sites per block
#define NS 16      // computed sites (1 halo + 15 owned) -> one m16 tile
#define NTILE 9    // ceil(128/15)
#define TPB 512
#define TOUT 107   // T-1-20

// Persistent double-buffered recurrent state
__device__ float g_hn[2][B*S*NH];
__device__ float g_cn[2][B*S*NH];
__device__ float g_hs[2][B*S*NH];
__device__ float g_cs[2][B*S*NH];
__device__ float g_hd[2][B*S*DH];
__device__ float g_cd[2][B*S*DH];

// Fragment-ordered bf16 weights (single-precision bf16, no lo term):
// entry (kt,nt,lane) = {b0, b1}
__device__ uint2 fBn[12*32*32];
__device__ uint2 fBs[12*32*32];
__device__ uint2 fBd[32*64*32];

// ---- shared memory layout (floats) ----
#define OFF_XIN 0                 // 16*4
#define OFF_O0  (OFF_XIN + 64)    // 16
#define OFF_O1  (OFF_O0 + 16)     // 16
#define OFF_HDC (OFF_O1 + 16)     // 16*128 = 2048
#define OFF_R1  (OFF_HDC + 2048)  // ns A frags (3072 uints) / gd (8192 floats) overlay
#define OFF_R2  (OFF_R1 + 8192)   // gn (4096) + gs (4096)
#define OFF_R3  (OFF_R2 + 8192)   // Ad frags (4096 uints)
#define SMEM_FLOATS (OFF_R3 + 4096)

#define MMA4(c, a0,a1,a2,a3, b0,b1) \
  asm volatile("mma.sync.aligned.m16n8k16.row.col.f32.bf16.bf16.f32 " \
    "{%0,%1,%2,%3}, {%4,%5,%6,%7}, {%8,%9}, {%0,%1,%2,%3};" \
    : "+f"(c[0]), "+f"(c[1]), "+f"(c[2]), "+f"(c[3]) \
    : "r"(a0), "r"(a1), "r"(a2), "r"(a3), "r"(b0), "r"(b1))

__device__ __forceinline__ float sigm(float x) { return 1.f / (1.f + __expf(-x)); }

__device__ __forceinline__ uint packbf2(float a, float b) {
    __nv_bfloat16 ha = __float2bfloat16_rn(a);
    __nv_bfloat16 hb = __float2bfloat16_rn(b);
    __nv_bfloat16_raw ra = *(__nv_bfloat16_raw*)&ha;
    __nv_bfloat16_raw rb = *(__nv_bfloat16_raw*)&hb;
    return (uint)ra.x | ((uint)rb.x << 16);
}

// write one bf16 element into fragment-ordered array at logical (row r, col k)
__device__ __forceinline__ void store_frag(__nv_bfloat16* Fb, int r, int k, float v) {
    int kt = k >> 4, ec = k & 15;
    int reg = ((ec >> 3) << 1) | (r >> 3);
    int ln  = ((r & 7) << 2) | ((ec & 7) >> 1);
    int idx = ((((kt << 5) + ln) << 2) + reg) * 2 + (ec & 1);
    Fb[idx] = __float2bfloat16_rn(v);
}

__global__ void init_states_kernel() {
    int i = blockIdx.x * blockDim.x + threadIdx.x;
    if (i < B*S*NH) {
        g_hn[0][i] = 0.f; g_cn[0][i] = 0.f;
        g_hs[0][i] = 0.f; g_cs[0][i] = 0.f;
    }
    if (i < B*S*DH) {
        g_hd[0][i] = 0.f; g_cd[0][i] = 0.f;
    }
}

__global__ void repack_kernel(
    const float* __restrict__ nWh, const float* __restrict__ nWa, const float* __restrict__ nWb,
    const float* __restrict__ sWh, const float* __restrict__ sWa, const float* __restrict__ sWb,
    const float* __restrict__ dWx, const float* __restrict__ dWh,
    const float* __restrict__ dWa, const float* __restrict__ dWb)
{
    int idx = blockIdx.x * blockDim.x + threadIdx.x;
    if (idx < 32*64*32) {
        int lane = idx & 31, nt = (idx >> 5) & 63, kt = idx >> 11;
        int n = nt*8 + (lane >> 2);
        int k0 = kt*16 + (lane & 3)*2;
        float v[4];
        #pragma unroll
        for (int j = 0; j < 4; j++) {
            int kk = k0 + (j >> 1)*8 + (j & 1);
            float x;
            if      (kk < 128) x = dWx[kk*512 + n];
            else if (kk < 256) x = dWh[(kk-128)*512 + n];
            else if (kk < 384) x = dWa[(kk-256)*512 + n];
            else               x = dWb[(kk-384)*512 + n];
            v[j] = x;
        }
        fBd[idx] = make_uint2(packbf2(v[0], v[1]), packbf2(v[2], v[3]));
    }
    int idx2 = idx - 32*64*32;
    if (idx2 >= 0 && idx2 < 2*12*32*32) {
        int set = idx2 / (12*32*32);
        int e = idx2 % (12*32*32);
        int lane = e & 31, nt = (e >> 5) & 31, kt = e >> 10;
        int n = nt*8 + (lane >> 2);
        int k0 = kt*16 + (lane & 3)*2;
        const float* Wh = set ? sWh : nWh;
        const float* Wa = set ? sWa : nWa;
        const float* Wb = set ? sWb : nWb;
        float v[4];
        #pragma unroll
        for (int j = 0; j < 4; j++) {
            int kk = k0 + (j >> 1)*8 + (j & 1);
            float x;
            if      (kk < 64)  x = Wh[kk*256 + n];
            else if (kk < 128) x = Wa[(kk-64)*256 + n];
            else               x = Wb[(kk-128)*256 + n];
            v[j] = x;
        }
        (set ? fBs : fBn)[e] = make_uint2(packbf2(v[0], v[1]), packbf2(v[2], v[3]));
    }
}

__global__ void __launch_bounds__(TPB, 1) step_kernel(
    const float* __restrict__ xg,
    const float* __restrict__ nWx, const float* __restrict__ nb,
    const float* __restrict__ sWx, const float* __restrict__ sb,
    const float* __restrict__ db,
    const float* __restrict__ onW, const float* __restrict__ onb,
    const float* __restrict__ osW, const float* __restrict__ osb,
    float* __restrict__ out, int t)
{
    extern __shared__ float sm[];
    float* xin = sm + OFF_XIN;
    float* o0s = sm + OFF_O0;
    float* o1s = sm + OFF_O1;
    float* hdc = sm + OFF_HDC;
    uint*  nsFu = (uint*)(sm + OFF_R1);    // An_h [0,1536), As_h [1536,3072)
    uint4* nsF4 = (uint4*)(sm + OFF_R1);
    float* gd   = sm + OFF_R1;             // overlay (used after ns frags dead)
    float* gn   = sm + OFF_R2;
    float* gs   = gn + NS*256;
    uint*  AdFu = (uint*)(sm + OFF_R3);
    uint4* AdF4 = (uint4*)(sm + OFF_R3);
    __nv_bfloat16* AdFb = (__nv_bfloat16*)AdFu;

    const int tid  = threadIdx.x;
    const int w    = tid >> 5;
    const int lane = tid & 31;
    const int bb   = blockIdx.y;
    const int s0   = blockIdx.x * TS;
    const int pp   = t & 1;
    const int qq   = pp ^ 1;

    const float* hnG = g_hn[pp] + bb*S*NH;
    const float* hsG = g_hs[pp] + bb*S*NH;
    const float* hdG = g_hd[pp] + bb*S*DH;

    // ---- P0: xin + build all A fragments directly from global state ----
    for (int i = tid; i < NS*4; i += TPB) {
        int r = i >> 2; int sg = s0 - 1 + r;
        xin[i] = ((unsigned)sg < (unsigned)S)
                 ? xg[(((size_t)bb*T + t)*S + sg)*4 + (i & 3)] : 0.f;
    }
    // ns A frags: units (kt 0..11, ln, reg)
    for (int u = tid; u < 12*32*4; u += TPB) {
        int kt = u >> 7, rem = u & 127, ln = rem >> 2, reg = rem & 3;
        int r = (ln >> 2) | ((reg & 1) << 3);
        int k = kt*16 + ((ln & 3) << 1) + ((reg >> 1) << 3);
        int site, kk;
        if (k < 64)       { site = s0 - 1 + r; kk = k; }
        else if (k < 128) { site = s0 + r;     kk = k - 64; }
        else              { site = s0 - 2 + r; kk = k - 128; }
        bool v = ((unsigned)site < (unsigned)S);
        float2 vn = v ? *(const float2*)&hnG[site*NH + kk] : make_float2(0.f, 0.f);
        float2 vs = v ? *(const float2*)&hsG[site*NH + kk] : make_float2(0.f, 0.f);
        int base = (kt*32 + ln)*4 + reg;
        nsFu[base]        = packbf2(vn.x, vn.y);
        nsFu[1536 + base] = packbf2(vs.x, vs.y);
    }
    // Ad halo frags: kt 8..31 (K in [128,512), depends only on prev hd)
    for (int u = tid; u < 24*32*4; u += TPB) {
        int kt = 8 + (u >> 7), rem = u & 127, ln = rem >> 2, reg = rem & 3;
        int r = (ln >> 2) | ((reg & 1) << 3);
        int k = kt*16 + ((ln & 3) << 1) + ((reg >> 1) << 3);
        int site, kk;
        if (k < 256)      { site = s0 - 1 + r; kk = k - 128; }
        else if (k < 384) { site = s0 + r;     kk = k - 256; }
        else              { site = s0 - 2 + r; kk = k - 384; }
        bool v = ((unsigned)site < (unsigned)S);
        float2 vd = v ? *(const float2*)&hdG[site*DH + kk] : make_float2(0.f, 0.f);
        AdFu[(kt*32 + ln)*4 + reg] = packbf2(vd.x, vd.y);
    }
    __syncthreads();

    // ---- P1: ns-GEMM + d-GEMM part 1 (kt 8..31), one long mma stream ----
    float dacc[4][4];
    #pragma unroll
    for (int j = 0; j < 4; j++)
        #pragma unroll
        for (int c = 0; c < 4; c++) dacc[j][c] = 0.f;
    {
        const int set = w >> 3, grp = w & 7;
        const uint4* Ah4 = nsF4 + set*384;
        const uint2* Bf = set ? fBs : fBn;
        float acc[4][4];
        #pragma unroll
        for (int j = 0; j < 4; j++)
            #pragma unroll
            for (int c = 0; c < 4; c++) acc[j][c] = 0.f;

        for (int kt = 0; kt < 12; kt++) {
            uint4 ah = Ah4[kt*32 + lane];
            #pragma unroll
            for (int j = 0; j < 4; j++) {
                uint2 bv = __ldg(&Bf[(kt*32 + grp*4 + j)*32 + lane]);
                MMA4(acc[j], ah.x, ah.y, ah.z, ah.w, bv.x, bv.y);
            }
        }
        float* g = set ? gs : gn;
        int site0 = lane >> 2, cb = (lane & 3)*2;
        #pragma unroll
        for (int j = 0; j < 4; j++) {
            int c0 = (grp*4 + j)*8 + cb;
            *(float2*)&g[site0*256 + c0]     = make_float2(acc[j][0], acc[j][1]);
            *(float2*)&g[(site0+8)*256 + c0] = make_float2(acc[j][2], acc[j][3]);
        }
        // d part 1
        for (int kt = 8; kt < 32; kt++) {
            uint4 ah = AdF4[kt*32 + lane];
            #pragma unroll
            for (int j = 0; j < 4; j++) {
                uint2 bv = __ldg(&fBd[(kt*64 + w*4 + j)*32 + lane]);
                MMA4(dacc[j], ah.x, ah.y, ah.z, ah.w, bv.x, bv.y);
            }
        }
    }
    __syncthreads();

    // ---- P2: n/s cell updates; h results stored straight into Ad frags ----
    for (int i = tid; i < NS*NH; i += TPB) {
        int r = i >> 6, e = i & 63;
        int sg = s0 - 1 + r;
        bool v = ((unsigned)sg < (unsigned)S);
        int gi = v ? (bb*S + sg)*NH + e : 0;
        float xr0 = xin[r*4+0], xr1 = xin[r*4+1], xr2 = xin[r*4+2], xr3 = xin[r*4+3];
        {
            float ii = gn[r*256 + e]      + nb[e]      + xr0*nWx[e]      + xr1*nWx[256+e]  + xr2*nWx[512+e];
            float ff = gn[r*256 + 64+e]   + nb[64+e]   + xr0*nWx[64+e]   + xr1*nWx[320+e]  + xr2*nWx[576+e];
            float uu = gn[r*256 + 128+e]  + nb[128+e]  + xr0*nWx[128+e]  + xr1*nWx[384+e]  + xr2*nWx[640+e];
            float oo = gn[r*256 + 192+e]  + nb[192+e]  + xr0*nWx[192+e]  + xr1*nWx[448+e]  + xr2*nWx[704+e];
            float cp = v ? g_cn[pp][gi] : 0.f;
            float c2 = sigm(ff)*cp + sigm(ii)*tanhf(uu);
            float hh = sigm(oo)*tanhf(c2);
            if (!v) { c2 = 0.f; hh = 0.f; }
            store_frag(AdFb, r, e, hh);
            if (r >= 1 && v) { g_cn[qq][gi] = c2; g_hn[qq][gi] = hh; }
        }
        {
            float ii = gs[r*256 + e]      + sb[e]      + xr3*sWx[e];
            float ff = gs[r*256 + 64+e]   + sb[64+e]   + xr3*sWx[64+e];
            float uu = gs[r*256 + 128+e]  + sb[128+e]  + xr3*sWx[128+e];
            float oo = gs[r*256 + 192+e]  + sb[192+e]  + xr3*sWx[192+e];
            float cp = v ? g_cs[pp][gi] : 0.f;
            float c2 = sigm(ff)*cp + sigm(ii)*tanhf(uu);
            float hh = sigm(oo)*tanhf(c2);
            if (!v) { c2 = 0.f; hh = 0.f; }
            store_frag(AdFb, r, 64 + e, hh);
            if (r >= 1 && v) { g_cs[qq][gi] = c2; g_hs[qq][gi] = hh; }
        }
    }
    __syncthreads();

    // ---- P3: d-GEMM part 2 (kt 0..7), write gd ----
    {
        for (int kt = 0; kt < 8; kt++) {
            uint4 ah = AdF4[kt*32 + lane];
            #pragma unroll
            for (int j = 0; j < 4; j++) {
                uint2 bv = __ldg(&fBd[(kt*64 + w*4 + j)*32 + lane]);
                MMA4(dacc[j], ah.x, ah.y, ah.z, ah.w, bv.x, bv.y);
            }
        }
        int site0 = lane >> 2, cb = (lane & 3)*2;
        #pragma unroll
        for (int j = 0; j < 4; j++) {
            int c0 = (w*4 + j)*8 + cb;
            *(float2*)&gd[site0*512 + c0]     = make_float2(dacc[j][0], dacc[j][1]);
            *(float2*)&gd[(site0+8)*512 + c0] = make_float2(dacc[j][2], dacc[j][3]);
        }
    }
    __syncthreads();

    // ---- P4: d cell update (+bias fold) ----
    for (int i = tid; i < NS*DH; i += TPB) {
        int r = i >> 7, e = i & 127;
        int sg = s0 - 1 + r;
        bool v = ((unsigned)sg < (unsigned)S);
        int gi = v ? (bb*S + sg)*DH + e : 0;
        float ii = gd[r*512 + e]       + db[e];
        float ff = gd[r*512 + 128 + e] + db[128+e];
        float uu = gd[r*512 + 256 + e] + db[256+e];
        float oo = gd[r*512 + 384 + e] + db[384+e];
        float cp = v ? g_cd[pp][gi] : 0.f;
        float c2 = sigm(ff)*cp + sigm(ii)*tanhf(uu);
        float hh = sigm(oo)*tanhf(c2);
        if (!v) { c2 = 0.f; hh = 0.f; }
        hdc[i] = hh;
        if (r >= 1 && v) { g_cd[qq][gi] = c2; g_hd[qq][gi] = hh; }
    }
    __syncthreads();

    // ---- P5: output heads, warp-parallel dot products ----
    for (int task = w; task < 32; task += 16) {
        int r = task & 15;
        int which = task >> 4;
        const float* W = which ? osW : onW;
        float a = 0.f;
        #pragma unroll
        for (int kk = lane; kk < DH; kk += 32) a += hdc[r*DH + kk] * W[kk];
        #pragma unroll
        for (int d = 16; d >= 1; d >>= 1) a += __shfl_xor_sync(0xffffffffu, a, d);
        if (lane == 0) {
            if (which) o1s[r] = a + osb[0];
            else       o0s[r] = a + onb[0];
        }
    }
    __syncthreads();

    // ---- P6: assemble next-input record and write output for t >= 20 ----
    if (t >= 20 && tid >= 1 && tid <= TS) {
        int r = tid;
        int sg = s0 + r - 1;
        if (sg < S) {
            float o0 = o0s[r];
            float o1 = o1s[r];
            float inflow, spd;
            if (sg == 0) {
                inflow = xg[(((size_t)bb*T + (t+1))*S + 0)*4 + 1];
                spd    = xg[(((size_t)bb*T + (t+1))*S + 0)*4 + 3];
            } else {
                inflow = o0s[r-1];
                spd    = o1;
            }
            float numc = xin[r*4 + 2] + inflow - o0;
            float* o = out + ((((size_t)bb*TOUT) + (t - 20))*S + sg)*4;
            o[0] = o0; o[1] = inflow; o[2] = numc; o[3] = spd;
        }
    }
}

extern "C" void kernel_launch(void* const* d_in, const int* in_sizes, int n_in,
                              void* d_out, int out_size) {
    const float* xg  = (const float*)d_in[0];
    const float* nWx = (const float*)d_in[1];
    const float* nWh = (const float*)d_in[2];
    const float* nWa = (const float*)d_in[3];
    const float* nWb = (const float*)d_in[4];
    const float* nb  = (const float*)d_in[5];
    const float* sWx = (const float*)d_in[6];
    const float* sWh = (const float*)d_in[7];
    const float* sWa = (const float*)d_in[8];
    const float* sWb = (const float*)d_in[9];
    const float* sb  = (const float*)d_in[10];
    const float* dWx = (const float*)d_in[11];
    const float* dWh = (const float*)d_in[12];
    const float* dWa = (const float*)d_in[13];
    const float* dWb = (const float*)d_in[14];
    const float* db  = (const float*)d_in[15];
    const float* onW = (const float*)d_in[16];
    const float* onb = (const float*)d_in[17];
    const float* osW = (const float*)d_in[18];
    const float* osb = (const float*)d_in[19];
    float* out = (float*)d_out;

    (void)in_sizes; (void)n_in; (void)out_size;

    const int smem_bytes = SMEM_FLOATS * (int)sizeof(float);
    cudaFuncSetAttribute(step_kernel,
                         cudaFuncAttributeMaxDynamicSharedMemorySize, smem_bytes);

    init_states_kernel<<<(B*S*DH + 255) / 256, 256>>>();
    int repack_threads = 32*64*32 + 2*12*32*32;
    repack_kernel<<<(repack_threads + 255) / 256, 256>>>(
        nWh, nWa, nWb, sWh, sWa, sWb, dWx, dWh, dWa, dWb);

    dim3 grid(NTILE, B);
    for (int t = 0; t < T - 1; ++t) {
        step_kernel<<<grid, TPB, smem_bytes>>>(
            xg, nWx, nb, sWx, sb, db,
            onW, onb, osW, osb, out, t);
    }
}